// round 4
// baseline (speedup 1.0000x reference)
#include <cuda_runtime.h>
#include <math.h>

#define NN 4096
#define CH 256
#define NH 8
#define DD 32           // CH / NH
#define QROW 260        // padded smem row (65 x 16B, odd quad stride -> conflict-free)
#define SMEM_BYTES (3 * 32 * QROW * 4)

// device scratch (allocation-free rule: __device__ globals)
__device__ float g_Q[NN * CH];
__device__ float g_K[NN * CH];
__device__ float g_V[NN * CH];
__device__ float g_AO[NN * DD];

// ---------------------------------------------------------------------------
// Kernel 1: Q/K/V projections.  out = X @ W + b.  grid = (64, 4, 3)
// ---------------------------------------------------------------------------
__global__ __launch_bounds__(256) void qkv_kernel(
    const float* __restrict__ X,
    const float* __restrict__ Wq, const float* __restrict__ bq,
    const float* __restrict__ Wk, const float* __restrict__ bk,
    const float* __restrict__ Wv, const float* __restrict__ bv)
{
    __shared__ float As[16][64];   // As[k][m]
    __shared__ float Bs[16][64];   // Bs[k][n]

    const float* W;
    const float* b;
    float* out;
    if (blockIdx.z == 0)      { W = Wq; b = bq; out = g_Q; }
    else if (blockIdx.z == 1) { W = Wk; b = bk; out = g_K; }
    else                      { W = Wv; b = bv; out = g_V; }

    const int m0 = blockIdx.x * 64;
    const int n0 = blockIdx.y * 64;
    const int tid = threadIdx.x;
    const int tx = tid & 15, ty = tid >> 4;

    float acc[4][4] = {};

    for (int k0 = 0; k0 < CH; k0 += 16) {
        {
            int k = tid & 15, mb = tid >> 4;
#pragma unroll
            for (int s = 0; s < 4; s++) {
                int m = mb + 16 * s;
                As[k][m] = X[(m0 + m) * CH + k0 + k];
            }
        }
        {
            int n = tid & 63, kb = tid >> 6;
#pragma unroll
            for (int s = 0; s < 4; s++) {
                int k = kb + 4 * s;
                Bs[k][n] = W[(k0 + k) * CH + n0 + n];
            }
        }
        __syncthreads();
#pragma unroll
        for (int k = 0; k < 16; k++) {
            float4 a4 = *(const float4*)&As[k][ty * 4];
            float4 b4 = *(const float4*)&Bs[k][tx * 4];
            float av[4] = {a4.x, a4.y, a4.z, a4.w};
            float bw[4] = {b4.x, b4.y, b4.z, b4.w};
#pragma unroll
            for (int i = 0; i < 4; i++)
#pragma unroll
                for (int j = 0; j < 4; j++)
                    acc[i][j] += av[i] * bw[j];
        }
        __syncthreads();
    }
#pragma unroll
    for (int i = 0; i < 4; i++) {
        int m = m0 + ty * 4 + i;
#pragma unroll
        for (int j = 0; j < 4; j++) {
            int n = n0 + tx * 4 + j;
            out[m * CH + n] = acc[i][j] + b[n];
        }
    }
}

// ---------------------------------------------------------------------------
// Kernel 2: fused scores + head-softmax + attn write + AV accumulation.
// grid = 128 blocks (32 i-rows each), 256 threads (16x16), j in chunks of 32.
// ---------------------------------------------------------------------------
__global__ __launch_bounds__(256, 1) void attn_kernel(
    const float* __restrict__ rel, float* __restrict__ attn_g)
{
    extern __shared__ float sm[];
    float* Qs = sm;                  // [32][QROW]
    float* Ks = sm + 32 * QROW;      // [32][QROW]
    float* Vs = sm + 2 * 32 * QROW;  // [32][QROW]

    const int tid = threadIdx.x;
    const int tx = tid & 15, ty = tid >> 4;
    const int ibase = blockIdx.x * 32;

    // load Q strip (once)
    for (int idx = tid; idx < 32 * 64; idx += 256) {
        int r = idx >> 6, c4 = idx & 63;
        *(float4*)&Qs[r * QROW + c4 * 4] =
            *(const float4*)&g_Q[(ibase + r) * CH + c4 * 4];
    }

    float ao[2][DD];
#pragma unroll
    for (int ii = 0; ii < 2; ii++)
#pragma unroll
        for (int d = 0; d < DD; d++) ao[ii][d] = 0.f;

    const float* q0p = &Qs[(ty * 2 + 0) * QROW];
    const float* q1p = &Qs[(ty * 2 + 1) * QROW];
    const float* k0p = &Ks[tx * QROW];
    const float* k1p = &Ks[(tx + 16) * QROW];
    const float* v0p = &Vs[tx * QROW];
    const float* v1p = &Vs[(tx + 16) * QROW];

    for (int jc = 0; jc < NN / 32; jc++) {
        const int jbase = jc * 32;
        __syncthreads();   // previous chunk's compute done (also covers Q load)
        for (int idx = tid; idx < 32 * 64; idx += 256) {
            int r = idx >> 6, c4 = idx & 63;
            *(float4*)&Ks[r * QROW + c4 * 4] =
                *(const float4*)&g_K[(jbase + r) * CH + c4 * 4];
            *(float4*)&Vs[r * QROW + c4 * 4] =
                *(const float4*)&g_V[(jbase + r) * CH + c4 * 4];
        }
        __syncthreads();

        // ---- scores: 2i x 2j x 8h ----
        float acc[2][2][NH];
#pragma unroll
        for (int ii = 0; ii < 2; ii++)
#pragma unroll
            for (int jj = 0; jj < 2; jj++)
#pragma unroll
                for (int h = 0; h < NH; h++) acc[ii][jj][h] = 0.f;

#pragma unroll 8
        for (int c8 = 0; c8 < 32; c8++) {
            const int base = c8 * 8;
            float q0[8], q1[8], k0[8], k1[8];
            *(float4*)&q0[0] = *(const float4*)(q0p + base);
            *(float4*)&q0[4] = *(const float4*)(q0p + base + 4);
            *(float4*)&q1[0] = *(const float4*)(q1p + base);
            *(float4*)&q1[4] = *(const float4*)(q1p + base + 4);
            *(float4*)&k0[0] = *(const float4*)(k0p + base);
            *(float4*)&k0[4] = *(const float4*)(k0p + base + 4);
            *(float4*)&k1[0] = *(const float4*)(k1p + base);
            *(float4*)&k1[4] = *(const float4*)(k1p + base + 4);
#pragma unroll
            for (int h = 0; h < 8; h++) {
                acc[0][0][h] += q0[h] * k0[h];
                acc[0][1][h] += q0[h] * k1[h];
                acc[1][0][h] += q1[h] * k0[h];
                acc[1][1][h] += q1[h] * k1[h];
            }
        }

        // ---- add rel, softmax over heads, write attn (in-place into acc) ----
#pragma unroll
        for (int ii = 0; ii < 2; ii++) {
            const int ig = ibase + ty * 2 + ii;
#pragma unroll
            for (int jj = 0; jj < 2; jj++) {
                const int jg = jbase + tx + jj * 16;
                const size_t rb = ((size_t)ig * NN + jg) * NH;
                float4 r0 = *(const float4*)&rel[rb];
                float4 r1 = *(const float4*)&rel[rb + 4];
                float s[8];
                s[0] = acc[ii][jj][0] + r0.x;  s[1] = acc[ii][jj][1] + r0.y;
                s[2] = acc[ii][jj][2] + r0.z;  s[3] = acc[ii][jj][3] + r0.w;
                s[4] = acc[ii][jj][4] + r1.x;  s[5] = acc[ii][jj][5] + r1.y;
                s[6] = acc[ii][jj][6] + r1.z;  s[7] = acc[ii][jj][7] + r1.w;
                float m = s[0];
#pragma unroll
                for (int h = 1; h < 8; h++) m = fmaxf(m, s[h]);
                float sum = 0.f;
#pragma unroll
                for (int h = 0; h < 8; h++) { s[h] = __expf(s[h] - m); sum += s[h]; }
                const float inv = 1.f / sum;
#pragma unroll
                for (int h = 0; h < 8; h++) acc[ii][jj][h] = s[h] * inv;
                float4 o0 = make_float4(acc[ii][jj][0], acc[ii][jj][1],
                                        acc[ii][jj][2], acc[ii][jj][3]);
                float4 o1 = make_float4(acc[ii][jj][4], acc[ii][jj][5],
                                        acc[ii][jj][6], acc[ii][jj][7]);
                *(float4*)&attn_g[rb]     = o0;
                *(float4*)&attn_g[rb + 4] = o1;
            }
        }

        // ---- AV: ao[ii][dd] += sum_h attn * V[j, dd*8+h] (V row shared by both i) ----
#pragma unroll
        for (int jj = 0; jj < 2; jj++) {
            const float* vp = (jj == 0) ? v0p : v1p;
#pragma unroll 4
            for (int dd = 0; dd < DD; dd++) {
                float vv[8];
                *(float4*)&vv[0] = *(const float4*)(vp + dd * 8);
                *(float4*)&vv[4] = *(const float4*)(vp + dd * 8 + 4);
                float s0 = 0.f, s1 = 0.f;
#pragma unroll
                for (int h = 0; h < 8; h++) {
                    s0 += acc[0][jj][h] * vv[h];
                    s1 += acc[1][jj][h] * vv[h];
                }
                ao[0][dd] += s0;
                ao[1][dd] += s1;
            }
        }
    }

    // ---- reduce ao across the 16 tx lanes (butterfly stays inside each half) ----
#pragma unroll
    for (int ii = 0; ii < 2; ii++)
#pragma unroll
        for (int dd = 0; dd < DD; dd++) {
            float v = ao[ii][dd];
            v += __shfl_xor_sync(0xffffffffu, v, 1);
            v += __shfl_xor_sync(0xffffffffu, v, 2);
            v += __shfl_xor_sync(0xffffffffu, v, 4);
            v += __shfl_xor_sync(0xffffffffu, v, 8);
            ao[ii][dd] = v;
        }
    if (tx == 0) {
#pragma unroll
        for (int ii = 0; ii < 2; ii++) {
            const int ig = ibase + ty * 2 + ii;
#pragma unroll
            for (int d4 = 0; d4 < DD; d4 += 4)
                *(float4*)&g_AO[ig * DD + d4] =
                    make_float4(ao[ii][d4], ao[ii][d4 + 1],
                                ao[ii][d4 + 2], ao[ii][d4 + 3]);
        }
    }
}

// ---------------------------------------------------------------------------
// Kernel 3: out = relu(ao @ W1 + b1) @ W2 + b2.  grid = 256 blocks x 16 rows.
// ---------------------------------------------------------------------------
__global__ __launch_bounds__(256) void mlp_kernel(
    const float* __restrict__ W1, const float* __restrict__ b1,
    const float* __restrict__ W2, const float* __restrict__ b2,
    float* __restrict__ out)
{
    __shared__ float aos[16][DD];
    __shared__ float hs[16][CH];

    const int tid = threadIdx.x;
    const int r0 = blockIdx.x * 16;

    for (int idx = tid; idx < 16 * DD; idx += 256)
        aos[idx / DD][idx % DD] = g_AO[(r0 + idx / DD) * DD + idx % DD];
    __syncthreads();

    const int c = tid;  // output column 0..255
    float w[DD];
#pragma unroll
    for (int k = 0; k < DD; k++) w[k] = W1[k * CH + c];
    const float bb1 = b1[c];
#pragma unroll 4
    for (int r = 0; r < 16; r++) {
        float a = bb1;
#pragma unroll
        for (int k = 0; k < DD; k++) a += aos[r][k] * w[k];
        hs[r][c] = fmaxf(a, 0.f);
    }
    __syncthreads();

    float acc2[16];
    const float bb2 = b2[c];
#pragma unroll
    for (int r = 0; r < 16; r++) acc2[r] = bb2;
#pragma unroll 4
    for (int k = 0; k < CH; k++) {
        const float wv = W2[k * CH + c];
#pragma unroll
        for (int r = 0; r < 16; r++) acc2[r] += hs[r][k] * wv;
    }
#pragma unroll
    for (int r = 0; r < 16; r++) out[(r0 + r) * CH + c] = acc2[r];
}

// ---------------------------------------------------------------------------
extern "C" void kernel_launch(void* const* d_in, const int* in_sizes, int n_in,
                              void* d_out, int out_size)
{
    const float* X   = (const float*)d_in[0];
    const float* rel = (const float*)d_in[1];
    // d_in[2] = num_nodes (unused; N fixed at 4096)
    const float* Wq = (const float*)d_in[3];
    const float* bq = (const float*)d_in[4];
    const float* Wk = (const float*)d_in[5];
    const float* bk = (const float*)d_in[6];
    const float* Wv = (const float*)d_in[7];
    const float* bv = (const float*)d_in[8];
    const float* W1 = (const float*)d_in[9];
    const float* b1 = (const float*)d_in[10];
    const float* W2 = (const float*)d_in[11];
    const float* b2 = (const float*)d_in[12];

    float* out    = (float*)d_out;           // [4096, 256]
    float* attn_g = out + (size_t)NN * CH;   // [4096, 4096, 8]

    cudaFuncSetAttribute(attn_kernel,
                         cudaFuncAttributeMaxDynamicSharedMemorySize, SMEM_BYTES);

    qkv_kernel<<<dim3(64, 4, 3), 256>>>(X, Wq, bq, Wk, bk, Wv, bv);
    attn_kernel<<<NN / 32, 256, SMEM_BYTES>>>(rel, attn_g);
    mlp_kernel<<<NN / 16, 256>>>(W1, b1, W2, b2, out);
}

// round 5
// speedup vs baseline: 1.0764x; 1.0764x over previous
#include <cuda_runtime.h>
#include <math.h>

#define NN 4096
#define CH 256
#define NH 8
#define DD 32           // CH / NH
#define QROW 260        // padded smem row (65 x 16B, odd quad stride -> conflict-free)
#define JC 64           // j-chunk
#define SMEM_BYTES ((32 + 2 * JC) * QROW * 4)

typedef unsigned long long u64;

// ---- packed f32x2 helpers (Blackwell FFMA2) ----
__device__ __forceinline__ u64 ffma2(u64 a, u64 b, u64 c) {
    u64 d;
    asm("fma.rn.f32x2 %0, %1, %2, %3;" : "=l"(d) : "l"(a), "l"(b), "l"(c));
    return d;
}
__device__ __forceinline__ u64 fmul2(u64 a, u64 b) {
    u64 d;
    asm("mul.rn.f32x2 %0, %1, %2;" : "=l"(d) : "l"(a), "l"(b));
    return d;
}
__device__ __forceinline__ float f2lo(u64 x) { return __uint_as_float((unsigned)x); }
__device__ __forceinline__ float f2hi(u64 x) { return __uint_as_float((unsigned)(x >> 32)); }
__device__ __forceinline__ u64 fpack(float l, float h) {
    return (u64)__float_as_uint(l) | ((u64)__float_as_uint(h) << 32);
}

// device scratch (allocation-free rule: __device__ globals)
__device__ float g_Q[NN * CH];
__device__ float g_K[NN * CH];
__device__ float g_V[NN * CH];
__device__ float g_AO[NN * DD];

// ---------------------------------------------------------------------------
// Kernel 1: Q/K/V projections.  out = X @ W + b.  grid = (64, 4, 3)
// ---------------------------------------------------------------------------
__global__ __launch_bounds__(256) void qkv_kernel(
    const float* __restrict__ X,
    const float* __restrict__ Wq, const float* __restrict__ bq,
    const float* __restrict__ Wk, const float* __restrict__ bk,
    const float* __restrict__ Wv, const float* __restrict__ bv)
{
    __shared__ float As[16][64];   // As[k][m]
    __shared__ float Bs[16][64];   // Bs[k][n]

    const float* W;
    const float* b;
    float* out;
    if (blockIdx.z == 0)      { W = Wq; b = bq; out = g_Q; }
    else if (blockIdx.z == 1) { W = Wk; b = bk; out = g_K; }
    else                      { W = Wv; b = bv; out = g_V; }

    const int m0 = blockIdx.x * 64;
    const int n0 = blockIdx.y * 64;
    const int tid = threadIdx.x;
    const int tx = tid & 15, ty = tid >> 4;

    float acc[4][4] = {};

    for (int k0 = 0; k0 < CH; k0 += 16) {
        {
            int k = tid & 15, mb = tid >> 4;
#pragma unroll
            for (int s = 0; s < 4; s++) {
                int m = mb + 16 * s;
                As[k][m] = X[(m0 + m) * CH + k0 + k];
            }
        }
        {
            int n = tid & 63, kb = tid >> 6;
#pragma unroll
            for (int s = 0; s < 4; s++) {
                int k = kb + 4 * s;
                Bs[k][n] = W[(k0 + k) * CH + n0 + n];
            }
        }
        __syncthreads();
#pragma unroll
        for (int k = 0; k < 16; k++) {
            float4 a4 = *(const float4*)&As[k][ty * 4];
            float4 b4 = *(const float4*)&Bs[k][tx * 4];
            float av[4] = {a4.x, a4.y, a4.z, a4.w};
            float bw[4] = {b4.x, b4.y, b4.z, b4.w};
#pragma unroll
            for (int i = 0; i < 4; i++)
#pragma unroll
                for (int j = 0; j < 4; j++)
                    acc[i][j] += av[i] * bw[j];
        }
        __syncthreads();
    }
#pragma unroll
    for (int i = 0; i < 4; i++) {
        int m = m0 + ty * 4 + i;
#pragma unroll
        for (int j = 0; j < 4; j++) {
            int n = n0 + tx * 4 + j;
            out[m * CH + n] = acc[i][j] + b[n];
        }
    }
}

// ---------------------------------------------------------------------------
// Kernel 2: fused scores + head-softmax + attn write + AV accumulation.
// grid = 128 blocks (32 i-rows each), 256 threads (16x16).
// j in chunks of 64; thread tile = 2i x 4j x 8h, packed f32x2 math.
// ---------------------------------------------------------------------------
__global__ __launch_bounds__(256, 1) void attn_kernel(
    const float* __restrict__ rel, float* __restrict__ attn_g)
{
    extern __shared__ float sm[];
    float* Qs = sm;                       // [32][QROW]
    float* Ks = sm + 32 * QROW;           // [JC][QROW]
    float* Vs = sm + (32 + JC) * QROW;    // [JC][QROW]

    const int tid = threadIdx.x;
    const int tx = tid & 15, ty = tid >> 4;
    const int ibase = blockIdx.x * 32;

    // load Q strip (once)
    for (int idx = tid; idx < 32 * 64; idx += 256) {
        int r = idx >> 6, c4 = idx & 63;
        *(float4*)&Qs[r * QROW + c4 * 4] =
            *(const float4*)&g_Q[(ibase + r) * CH + c4 * 4];
    }

    float ao[2][DD];
#pragma unroll
    for (int ii = 0; ii < 2; ii++)
#pragma unroll
        for (int d = 0; d < DD; d++) ao[ii][d] = 0.f;

    const float* q0p = &Qs[(ty * 2 + 0) * QROW];
    const float* q1p = &Qs[(ty * 2 + 1) * QROW];

    for (int jc = 0; jc < NN / JC; jc++) {
        const int jbase = jc * JC;
        __syncthreads();   // previous chunk's compute done (also covers Q load)
        for (int idx = tid; idx < JC * 64; idx += 256) {
            int r = idx >> 6, c4 = idx & 63;
            *(float4*)&Ks[r * QROW + c4 * 4] =
                *(const float4*)&g_K[(jbase + r) * CH + c4 * 4];
            *(float4*)&Vs[r * QROW + c4 * 4] =
                *(const float4*)&g_V[(jbase + r) * CH + c4 * 4];
        }
        __syncthreads();

        // ---- scores: 2i x 4j x 8h, f32x2-packed over head pairs ----
        u64 acc[2][4][4];
#pragma unroll
        for (int ii = 0; ii < 2; ii++)
#pragma unroll
            for (int jj = 0; jj < 4; jj++)
#pragma unroll
                for (int p = 0; p < 4; p++) acc[ii][jj][p] = 0ull;

        const float* kp0 = &Ks[(tx +  0) * QROW];
        const float* kp1 = &Ks[(tx + 16) * QROW];
        const float* kp2 = &Ks[(tx + 32) * QROW];
        const float* kp3 = &Ks[(tx + 48) * QROW];

#pragma unroll 4
        for (int c8 = 0; c8 < 32; c8++) {
            const int base = c8 * 8;
            u64 q0[4], q1[4];
            {
                ulonglong2 t0 = *(const ulonglong2*)(q0p + base);
                ulonglong2 t1 = *(const ulonglong2*)(q0p + base + 4);
                q0[0] = t0.x; q0[1] = t0.y; q0[2] = t1.x; q0[3] = t1.y;
                ulonglong2 u0 = *(const ulonglong2*)(q1p + base);
                ulonglong2 u1 = *(const ulonglong2*)(q1p + base + 4);
                q1[0] = u0.x; q1[1] = u0.y; q1[2] = u1.x; q1[3] = u1.y;
            }
            const float* kps[4] = {kp0, kp1, kp2, kp3};
#pragma unroll
            for (int jj = 0; jj < 4; jj++) {
                u64 kk[4];
                ulonglong2 t0 = *(const ulonglong2*)(kps[jj] + base);
                ulonglong2 t1 = *(const ulonglong2*)(kps[jj] + base + 4);
                kk[0] = t0.x; kk[1] = t0.y; kk[2] = t1.x; kk[3] = t1.y;
#pragma unroll
                for (int p = 0; p < 4; p++) {
                    acc[0][jj][p] = ffma2(q0[p], kk[p], acc[0][jj][p]);
                    acc[1][jj][p] = ffma2(q1[p], kk[p], acc[1][jj][p]);
                }
            }
        }

        // ---- add rel, softmax over heads, write attn, repack into acc ----
#pragma unroll
        for (int ii = 0; ii < 2; ii++) {
            const int ig = ibase + ty * 2 + ii;
#pragma unroll
            for (int jj = 0; jj < 4; jj++) {
                const int jg = jbase + tx + jj * 16;
                const size_t rb = ((size_t)ig * NN + jg) * NH;
                float4 r0 = *(const float4*)&rel[rb];
                float4 r1 = *(const float4*)&rel[rb + 4];
                float s[8];
                s[0] = f2lo(acc[ii][jj][0]) + r0.x;
                s[1] = f2hi(acc[ii][jj][0]) + r0.y;
                s[2] = f2lo(acc[ii][jj][1]) + r0.z;
                s[3] = f2hi(acc[ii][jj][1]) + r0.w;
                s[4] = f2lo(acc[ii][jj][2]) + r1.x;
                s[5] = f2hi(acc[ii][jj][2]) + r1.y;
                s[6] = f2lo(acc[ii][jj][3]) + r1.z;
                s[7] = f2hi(acc[ii][jj][3]) + r1.w;
                float m = s[0];
#pragma unroll
                for (int h = 1; h < 8; h++) m = fmaxf(m, s[h]);
                float sum = 0.f;
#pragma unroll
                for (int h = 0; h < 8; h++) { s[h] = __expf(s[h] - m); sum += s[h]; }
                const float inv = 1.f / sum;
#pragma unroll
                for (int h = 0; h < 8; h++) s[h] *= inv;
                *(float4*)&attn_g[rb]     = make_float4(s[0], s[1], s[2], s[3]);
                *(float4*)&attn_g[rb + 4] = make_float4(s[4], s[5], s[6], s[7]);
#pragma unroll
                for (int p = 0; p < 4; p++)
                    acc[ii][jj][p] = fpack(s[2 * p], s[2 * p + 1]);
            }
        }

        // ---- AV: ao[ii][dd] += sum_h attn * V[j, dd*8+h] (f32x2 packed) ----
#pragma unroll
        for (int jj = 0; jj < 4; jj++) {
            const float* vp = &Vs[(tx + 16 * jj) * QROW];
#pragma unroll 4
            for (int dd = 0; dd < DD; dd++) {
                u64 v2[4];
                ulonglong2 t0 = *(const ulonglong2*)(vp + dd * 8);
                ulonglong2 t1 = *(const ulonglong2*)(vp + dd * 8 + 4);
                v2[0] = t0.x; v2[1] = t0.y; v2[2] = t1.x; v2[3] = t1.y;
                u64 s0 = fmul2(acc[0][jj][0], v2[0]);
                s0 = ffma2(acc[0][jj][1], v2[1], s0);
                s0 = ffma2(acc[0][jj][2], v2[2], s0);
                s0 = ffma2(acc[0][jj][3], v2[3], s0);
                u64 s1 = fmul2(acc[1][jj][0], v2[0]);
                s1 = ffma2(acc[1][jj][1], v2[1], s1);
                s1 = ffma2(acc[1][jj][2], v2[2], s1);
                s1 = ffma2(acc[1][jj][3], v2[3], s1);
                ao[0][dd] += f2lo(s0) + f2hi(s0);
                ao[1][dd] += f2lo(s1) + f2hi(s1);
            }
        }
    }

    // ---- reduce ao across the 16 tx lanes (butterfly stays inside each half) ----
#pragma unroll
    for (int ii = 0; ii < 2; ii++)
#pragma unroll
        for (int dd = 0; dd < DD; dd++) {
            float v = ao[ii][dd];
            v += __shfl_xor_sync(0xffffffffu, v, 1);
            v += __shfl_xor_sync(0xffffffffu, v, 2);
            v += __shfl_xor_sync(0xffffffffu, v, 4);
            v += __shfl_xor_sync(0xffffffffu, v, 8);
            ao[ii][dd] = v;
        }
    if (tx == 0) {
#pragma unroll
        for (int ii = 0; ii < 2; ii++) {
            const int ig = ibase + ty * 2 + ii;
#pragma unroll
            for (int d4 = 0; d4 < DD; d4 += 4)
                *(float4*)&g_AO[ig * DD + d4] =
                    make_float4(ao[ii][d4], ao[ii][d4 + 1],
                                ao[ii][d4 + 2], ao[ii][d4 + 3]);
        }
    }
}

// ---------------------------------------------------------------------------
// Kernel 3: out = relu(ao @ W1 + b1) @ W2 + b2.  grid = 256 blocks x 16 rows.
// ---------------------------------------------------------------------------
__global__ __launch_bounds__(256) void mlp_kernel(
    const float* __restrict__ W1, const float* __restrict__ b1,
    const float* __restrict__ W2, const float* __restrict__ b2,
    float* __restrict__ out)
{
    __shared__ float aos[16][DD];
    __shared__ float hs[16][CH];

    const int tid = threadIdx.x;
    const int r0 = blockIdx.x * 16;

    for (int idx = tid; idx < 16 * DD; idx += 256)
        aos[idx / DD][idx % DD] = g_AO[(r0 + idx / DD) * DD + idx % DD];
    __syncthreads();

    const int c = tid;  // output column 0..255
    float w[DD];
#pragma unroll
    for (int k = 0; k < DD; k++) w[k] = W1[k * CH + c];
    const float bb1 = b1[c];
#pragma unroll 4
    for (int r = 0; r < 16; r++) {
        float a = bb1;
#pragma unroll
        for (int k = 0; k < DD; k++) a += aos[r][k] * w[k];
        hs[r][c] = fmaxf(a, 0.f);
    }
    __syncthreads();

    float acc2[16];
    const float bb2 = b2[c];
#pragma unroll
    for (int r = 0; r < 16; r++) acc2[r] = bb2;
#pragma unroll 4
    for (int k = 0; k < CH; k++) {
        const float wv = W2[k * CH + c];
#pragma unroll
        for (int r = 0; r < 16; r++) acc2[r] += hs[r][k] * wv;
    }
#pragma unroll
    for (int r = 0; r < 16; r++) out[(r0 + r) * CH + c] = acc2[r];
}

// ---------------------------------------------------------------------------
extern "C" void kernel_launch(void* const* d_in, const int* in_sizes, int n_in,
                              void* d_out, int out_size)
{
    const float* X   = (const float*)d_in[0];
    const float* rel = (const float*)d_in[1];
    // d_in[2] = num_nodes (unused; N fixed at 4096)
    const float* Wq = (const float*)d_in[3];
    const float* bq = (const float*)d_in[4];
    const float* Wk = (const float*)d_in[5];
    const float* bk = (const float*)d_in[6];
    const float* Wv = (const float*)d_in[7];
    const float* bv = (const float*)d_in[8];
    const float* W1 = (const float*)d_in[9];
    const float* b1 = (const float*)d_in[10];
    const float* W2 = (const float*)d_in[11];
    const float* b2 = (const float*)d_in[12];

    float* out    = (float*)d_out;           // [4096, 256]
    float* attn_g = out + (size_t)NN * CH;   // [4096, 4096, 8]

    cudaFuncSetAttribute(attn_kernel,
                         cudaFuncAttributeMaxDynamicSharedMemorySize, SMEM_BYTES);

    qkv_kernel<<<dim3(64, 4, 3), 256>>>(X, Wq, bq, Wk, bk, Wv, bv);
    attn_kernel<<<NN / 32, 256, SMEM_BYTES>>>(rel, attn_g);
    mlp_kernel<<<NN / 16, 256>>>(W1, b1, W2, b2, out);
}

// round 8
// speedup vs baseline: 1.4313x; 1.3297x over previous
#include <cuda_runtime.h>
#include <math.h>

#define NN 4096
#define CH 256
#define NH 8
#define DD 32           // CH / NH
#define QROW 260        // padded smem row (65 x 16B, odd quad stride -> conflict-free)
#define JC 32           // j-chunk
#define NSPLIT 7        // j-range splits (grid = 128*7 = 896 blocks ~ 3.03 waves @ occ2)
#define SMEM_BYTES ((32 + 2 * JC) * QROW * 4)   // 99840 B -> 2 blocks/SM

typedef unsigned long long u64;

// ---- packed f32x2 helpers (Blackwell FFMA2) ----
__device__ __forceinline__ u64 ffma2(u64 a, u64 b, u64 c) {
    u64 d;
    asm("fma.rn.f32x2 %0, %1, %2, %3;" : "=l"(d) : "l"(a), "l"(b), "l"(c));
    return d;
}
__device__ __forceinline__ u64 fmul2(u64 a, u64 b) {
    u64 d;
    asm("mul.rn.f32x2 %0, %1, %2;" : "=l"(d) : "l"(a), "l"(b));
    return d;
}
__device__ __forceinline__ float f2lo(u64 x) { return __uint_as_float((unsigned)x); }
__device__ __forceinline__ float f2hi(u64 x) { return __uint_as_float((unsigned)(x >> 32)); }
__device__ __forceinline__ u64 fpack(float l, float h) {
    return (u64)__float_as_uint(l) | ((u64)__float_as_uint(h) << 32);
}

// device scratch (allocation-free rule: __device__ globals)
__device__ float g_Q[NN * CH];
__device__ float g_K[NN * CH];
__device__ float g_V[NN * CH];
__device__ float g_AOp[NSPLIT][NN * DD];   // per-split partial attn_out

// ---------------------------------------------------------------------------
// Kernel 1: Q/K/V projections.  out = X @ W + b.  grid = (64, 4, 3)
// ---------------------------------------------------------------------------
__global__ __launch_bounds__(256) void qkv_kernel(
    const float* __restrict__ X,
    const float* __restrict__ Wq, const float* __restrict__ bq,
    const float* __restrict__ Wk, const float* __restrict__ bk,
    const float* __restrict__ Wv, const float* __restrict__ bv)
{
    __shared__ float As[16][64];   // As[k][m]
    __shared__ float Bs[16][64];   // Bs[k][n]

    const float* W;
    const float* b;
    float* out;
    if (blockIdx.z == 0)      { W = Wq; b = bq; out = g_Q; }
    else if (blockIdx.z == 1) { W = Wk; b = bk; out = g_K; }
    else                      { W = Wv; b = bv; out = g_V; }

    const int m0 = blockIdx.x * 64;
    const int n0 = blockIdx.y * 64;
    const int tid = threadIdx.x;
    const int tx = tid & 15, ty = tid >> 4;

    float acc[4][4] = {};

    for (int k0 = 0; k0 < CH; k0 += 16) {
        {
            int k = tid & 15, mb = tid >> 4;
#pragma unroll
            for (int s = 0; s < 4; s++) {
                int m = mb + 16 * s;
                As[k][m] = X[(m0 + m) * CH + k0 + k];
            }
        }
        {
            int n = tid & 63, kb = tid >> 6;
#pragma unroll
            for (int s = 0; s < 4; s++) {
                int k = kb + 4 * s;
                Bs[k][n] = W[(k0 + k) * CH + n0 + n];
            }
        }
        __syncthreads();
#pragma unroll
        for (int k = 0; k < 16; k++) {
            float4 a4 = *(const float4*)&As[k][ty * 4];
            float4 b4 = *(const float4*)&Bs[k][tx * 4];
            float av[4] = {a4.x, a4.y, a4.z, a4.w};
            float bw[4] = {b4.x, b4.y, b4.z, b4.w};
#pragma unroll
            for (int i = 0; i < 4; i++)
#pragma unroll
                for (int j = 0; j < 4; j++)
                    acc[i][j] += av[i] * bw[j];
        }
        __syncthreads();
    }
#pragma unroll
    for (int i = 0; i < 4; i++) {
        int m = m0 + ty * 4 + i;
#pragma unroll
        for (int j = 0; j < 4; j++) {
            int n = n0 + tx * 4 + j;
            out[m * CH + n] = acc[i][j] + b[n];
        }
    }
}

// ---------------------------------------------------------------------------
// Kernel 2: fused scores + head-softmax + attn write + AV accumulation.
// grid = (128 i-strips, NSPLIT j-splits), 256 threads (16x16), occ 2/SM.
// j in chunks of 32; thread tile = 2i x 2j x 8h, packed f32x2 math.
// ---------------------------------------------------------------------------
__global__ __launch_bounds__(256, 2) void attn_kernel(
    const float* __restrict__ rel, float* __restrict__ attn_g)
{
    extern __shared__ float sm[];
    float* Qs = sm;                       // [32][QROW]
    float* Ks = sm + 32 * QROW;           // [JC][QROW]
    float* Vs = sm + (32 + JC) * QROW;    // [JC][QROW]

    const int tid = threadIdx.x;
    const int tx = tid & 15, ty = tid >> 4;
    const int ibase = blockIdx.x * 32;
    const int split = blockIdx.y;

    const int NCH = NN / JC;                       // 128 chunks total
    const int c0 = (split * NCH) / NSPLIT;
    const int c1 = ((split + 1) * NCH) / NSPLIT;

    // load Q strip (once)
    for (int idx = tid; idx < 32 * 64; idx += 256) {
        int r = idx >> 6, c4 = idx & 63;
        *(float4*)&Qs[r * QROW + c4 * 4] =
            *(const float4*)&g_Q[(ibase + r) * CH + c4 * 4];
    }

    float ao[2][DD];
#pragma unroll
    for (int ii = 0; ii < 2; ii++)
#pragma unroll
        for (int d = 0; d < DD; d++) ao[ii][d] = 0.f;

    const float* q0p = &Qs[(ty * 2 + 0) * QROW];
    const float* q1p = &Qs[(ty * 2 + 1) * QROW];
    const float* k0p = &Ks[tx * QROW];
    const float* k1p = &Ks[(tx + 16) * QROW];
    const float* v0p = &Vs[tx * QROW];
    const float* v1p = &Vs[(tx + 16) * QROW];

    for (int jc = c0; jc < c1; jc++) {
        const int jbase = jc * JC;
        __syncthreads();   // previous chunk's compute done (also covers Q load)
        for (int idx = tid; idx < JC * 64; idx += 256) {
            int r = idx >> 6, c4 = idx & 63;
            *(float4*)&Ks[r * QROW + c4 * 4] =
                *(const float4*)&g_K[(jbase + r) * CH + c4 * 4];
            *(float4*)&Vs[r * QROW + c4 * 4] =
                *(const float4*)&g_V[(jbase + r) * CH + c4 * 4];
        }
        __syncthreads();

        // ---- scores: 2i x 2j x 8h, f32x2-packed over head pairs ----
        u64 acc[2][2][4];
#pragma unroll
        for (int ii = 0; ii < 2; ii++)
#pragma unroll
            for (int jj = 0; jj < 2; jj++)
#pragma unroll
                for (int p = 0; p < 4; p++) acc[ii][jj][p] = 0ull;

#pragma unroll 4
        for (int c8 = 0; c8 < 32; c8++) {
            const int base = c8 * 8;
            u64 q0[4], q1[4];
            {
                ulonglong2 t0 = *(const ulonglong2*)(q0p + base);
                ulonglong2 t1 = *(const ulonglong2*)(q0p + base + 4);
                q0[0] = t0.x; q0[1] = t0.y; q0[2] = t1.x; q0[3] = t1.y;
                ulonglong2 u0 = *(const ulonglong2*)(q1p + base);
                ulonglong2 u1 = *(const ulonglong2*)(q1p + base + 4);
                q1[0] = u0.x; q1[1] = u0.y; q1[2] = u1.x; q1[3] = u1.y;
            }
            {
                u64 kk[4];
                ulonglong2 t0 = *(const ulonglong2*)(k0p + base);
                ulonglong2 t1 = *(const ulonglong2*)(k0p + base + 4);
                kk[0] = t0.x; kk[1] = t0.y; kk[2] = t1.x; kk[3] = t1.y;
#pragma unroll
                for (int p = 0; p < 4; p++) {
                    acc[0][0][p] = ffma2(q0[p], kk[p], acc[0][0][p]);
                    acc[1][0][p] = ffma2(q1[p], kk[p], acc[1][0][p]);
                }
            }
            {
                u64 kk[4];
                ulonglong2 t0 = *(const ulonglong2*)(k1p + base);
                ulonglong2 t1 = *(const ulonglong2*)(k1p + base + 4);
                kk[0] = t0.x; kk[1] = t0.y; kk[2] = t1.x; kk[3] = t1.y;
#pragma unroll
                for (int p = 0; p < 4; p++) {
                    acc[0][1][p] = ffma2(q0[p], kk[p], acc[0][1][p]);
                    acc[1][1][p] = ffma2(q1[p], kk[p], acc[1][1][p]);
                }
            }
        }

        // ---- add rel, softmax over heads, write attn, repack into acc ----
#pragma unroll
        for (int ii = 0; ii < 2; ii++) {
            const int ig = ibase + ty * 2 + ii;
#pragma unroll
            for (int jj = 0; jj < 2; jj++) {
                const int jg = jbase + tx + jj * 16;
                const size_t rb = ((size_t)ig * NN + jg) * NH;
                float4 r0 = *(const float4*)&rel[rb];
                float4 r1 = *(const float4*)&rel[rb + 4];
                float s[8];
                s[0] = f2lo(acc[ii][jj][0]) + r0.x;
                s[1] = f2hi(acc[ii][jj][0]) + r0.y;
                s[2] = f2lo(acc[ii][jj][1]) + r0.z;
                s[3] = f2hi(acc[ii][jj][1]) + r0.w;
                s[4] = f2lo(acc[ii][jj][2]) + r1.x;
                s[5] = f2hi(acc[ii][jj][2]) + r1.y;
                s[6] = f2lo(acc[ii][jj][3]) + r1.z;
                s[7] = f2hi(acc[ii][jj][3]) + r1.w;
                float m = s[0];
#pragma unroll
                for (int h = 1; h < 8; h++) m = fmaxf(m, s[h]);
                float sum = 0.f;
#pragma unroll
                for (int h = 0; h < 8; h++) { s[h] = __expf(s[h] - m); sum += s[h]; }
                const float inv = 1.f / sum;
#pragma unroll
                for (int h = 0; h < 8; h++) s[h] *= inv;
                *(float4*)&attn_g[rb]     = make_float4(s[0], s[1], s[2], s[3]);
                *(float4*)&attn_g[rb + 4] = make_float4(s[4], s[5], s[6], s[7]);
#pragma unroll
                for (int p = 0; p < 4; p++)
                    acc[ii][jj][p] = fpack(s[2 * p], s[2 * p + 1]);
            }
        }

        // ---- AV: ao[ii][dd] += sum_h attn * V[j, dd*8+h] (f32x2 packed) ----
#pragma unroll
        for (int jj = 0; jj < 2; jj++) {
            const float* vp = (jj == 0) ? v0p : v1p;
#pragma unroll 4
            for (int dd = 0; dd < DD; dd++) {
                u64 v2[4];
                ulonglong2 t0 = *(const ulonglong2*)(vp + dd * 8);
                ulonglong2 t1 = *(const ulonglong2*)(vp + dd * 8 + 4);
                v2[0] = t0.x; v2[1] = t0.y; v2[2] = t1.x; v2[3] = t1.y;
                u64 s0 = fmul2(acc[0][jj][0], v2[0]);
                s0 = ffma2(acc[0][jj][1], v2[1], s0);
                s0 = ffma2(acc[0][jj][2], v2[2], s0);
                s0 = ffma2(acc[0][jj][3], v2[3], s0);
                u64 s1 = fmul2(acc[1][jj][0], v2[0]);
                s1 = ffma2(acc[1][jj][1], v2[1], s1);
                s1 = ffma2(acc[1][jj][2], v2[2], s1);
                s1 = ffma2(acc[1][jj][3], v2[3], s1);
                ao[0][dd] += f2lo(s0) + f2hi(s0);
                ao[1][dd] += f2lo(s1) + f2hi(s1);
            }
        }
    }

    // ---- reduce ao across the 16 tx lanes (butterfly stays inside each half) ----
#pragma unroll
    for (int ii = 0; ii < 2; ii++)
#pragma unroll
        for (int dd = 0; dd < DD; dd++) {
            float v = ao[ii][dd];
            v += __shfl_xor_sync(0xffffffffu, v, 1);
            v += __shfl_xor_sync(0xffffffffu, v, 2);
            v += __shfl_xor_sync(0xffffffffu, v, 4);
            v += __shfl_xor_sync(0xffffffffu, v, 8);
            ao[ii][dd] = v;
        }
    if (tx == 0) {
        float* aop = g_AOp[split];
#pragma unroll
        for (int ii = 0; ii < 2; ii++) {
            const int ig = ibase + ty * 2 + ii;
#pragma unroll
            for (int d4 = 0; d4 < DD; d4 += 4)
                *(float4*)&aop[ig * DD + d4] =
                    make_float4(ao[ii][d4], ao[ii][d4 + 1],
                                ao[ii][d4 + 2], ao[ii][d4 + 3]);
        }
    }
}

// ---------------------------------------------------------------------------
// Kernel 3: sum split partials, then out = relu(ao @ W1 + b1) @ W2 + b2.
// grid = 256 blocks x 16 rows.
// ---------------------------------------------------------------------------
__global__ __launch_bounds__(256) void mlp_kernel(
    const float* __restrict__ W1, const float* __restrict__ b1,
    const float* __restrict__ W2, const float* __restrict__ b2,
    float* __restrict__ out)
{
    __shared__ float aos[16][DD];
    __shared__ float hs[16][CH];

    const int tid = threadIdx.x;
    const int r0 = blockIdx.x * 16;

    for (int idx = tid; idx < 16 * DD; idx += 256) {
        const int off = (r0 + idx / DD) * DD + (idx % DD);
        float a = 0.f;
#pragma unroll
        for (int s = 0; s < NSPLIT; s++) a += g_AOp[s][off];
        aos[idx / DD][idx % DD] = a;
    }
    __syncthreads();

    const int c = tid;  // output column 0..255
    float w[DD];
#pragma unroll
    for (int k = 0; k < DD; k++) w[k] = W1[k * CH + c];
    const float bb1 = b1[c];
#pragma unroll 4
    for (int r = 0; r < 16; r++) {
        float a = bb1;
#pragma unroll
        for (int k = 0; k < DD; k++) a += aos[r][k] * w[k];
        hs[r][c] = fmaxf(a, 0.f);
    }
    __syncthreads();

    float acc2[16];
    const float bb2 = b2[c];
#pragma unroll
    for (int r = 0; r < 16; r++) acc2[r] = bb2;
#pragma unroll 4
    for (int k = 0; k < CH; k++) {
        const float wv = W2[k * CH + c];
#pragma unroll
        for (int r = 0; r < 16; r++) acc2[r] += hs[r][k] * wv;
    }
#pragma unroll
    for (int r = 0; r < 16; r++) out[(r0 + r) * CH + c] = acc2[r];
}

// ---------------------------------------------------------------------------
extern "C" void kernel_launch(void* const* d_in, const int* in_sizes, int n_in,
                              void* d_out, int out_size)
{
    const float* X   = (const float*)d_in[0];
    const float* rel = (const float*)d_in[1];
    // d_in[2] = num_nodes (unused; N fixed at 4096)
    const float* Wq = (const float*)d_in[3];
    const float* bq = (const float*)d_in[4];
    const float* Wk = (const float*)d_in[5];
    const float* bk = (const float*)d_in[6];
    const float* Wv = (const float*)d_in[7];
    const float* bv = (const float*)d_in[8];
    const float* W1 = (const float*)d_in[9];
    const float* b1 = (const float*)d_in[10];
    const float* W2 = (const float*)d_in[11];
    const float* b2 = (const float*)d_in[12];

    float* out    = (float*)d_out;           // [4096, 256]
    float* attn_g = out + (size_t)NN * CH;   // [4096, 4096, 8]

    cudaFuncSetAttribute(attn_kernel,
                         cudaFuncAttributeMaxDynamicSharedMemorySize, SMEM_BYTES);

    qkv_kernel<<<dim3(64, 4, 3), 256>>>(X, Wq, bq, Wk, bk, Wv, bv);
    attn_kernel<<<dim3(NN / 32, NSPLIT), 256, SMEM_BYTES>>>(rel, attn_g);
    mlp_kernel<<<NN / 16, 256>>>(W1, b1, W2, b2, out);
}

// round 11
// speedup vs baseline: 1.5877x; 1.1093x over previous
#include <cuda_runtime.h>
#include <math.h>

#define NN 4096
#define CH 256
#define NH 8
#define DD 32           // CH / NH
#define QROW 260        // padded smem row for V (odd quad stride -> conflict-free)
#define JC 32           // j-chunk in pass2
#define NSPLIT 7        // j-range splits

typedef unsigned long long u64;
typedef unsigned int u32;

// ---- packed f32x2 helpers (Blackwell) ----
__device__ __forceinline__ u64 ffma2(u64 a, u64 b, u64 c) {
    u64 d;
    asm("fma.rn.f32x2 %0, %1, %2, %3;" : "=l"(d) : "l"(a), "l"(b), "l"(c));
    return d;
}
__device__ __forceinline__ u64 fmul2(u64 a, u64 b) {
    u64 d;
    asm("mul.rn.f32x2 %0, %1, %2;" : "=l"(d) : "l"(a), "l"(b));
    return d;
}
__device__ __forceinline__ float f2lo(u64 x) { return __uint_as_float((unsigned)x); }
__device__ __forceinline__ float f2hi(u64 x) { return __uint_as_float((unsigned)(x >> 32)); }
__device__ __forceinline__ u64 fpack(float l, float h) {
    return (u64)__float_as_uint(l) | ((u64)__float_as_uint(h) << 32);
}
__device__ __forceinline__ float to_tf32(float v) {
    u32 r;
    asm("cvt.rna.tf32.f32 %0, %1;" : "=r"(r) : "f"(v));
    return __uint_as_float(r);
}

// ---- mma.sync m16n8k8 tf32 ----
__device__ __forceinline__ void mma_tf32(float c[4], const u32 a[4], const u32 b[2]) {
    asm("mma.sync.aligned.m16n8k8.row.col.f32.tf32.tf32.f32 "
        "{%0,%1,%2,%3}, {%4,%5,%6,%7}, {%8,%9}, {%0,%1,%2,%3};"
        : "+f"(c[0]), "+f"(c[1]), "+f"(c[2]), "+f"(c[3])
        : "r"(a[0]), "r"(a[1]), "r"(a[2]), "r"(a[3]), "r"(b[0]), "r"(b[1]));
}

// device scratch (allocation-free rule: __device__ globals)
__device__ float g_V[NN * CH];
__device__ float g_Qhi[NH * NN * DD];   // per-head tf32-rounded planes [h][i][dd]
__device__ float g_Qlo[NH * NN * DD];
__device__ float g_Khi[NH * NN * DD];
__device__ float g_Klo[NH * NN * DD];
__device__ float g_S[(size_t)NH * NN * NN];   // score planes [h][i][j]
__device__ float g_AOp[NSPLIT][NN * DD];      // per-split partial attn_out

// ---------------------------------------------------------------------------
// Kernel 1: Q/K/V projections. V -> g_V; Q,K -> tf32 hi/lo per-head planes.
// grid = (64, 4, 3)
// ---------------------------------------------------------------------------
__global__ __launch_bounds__(256) void qkv_kernel(
    const float* __restrict__ X,
    const float* __restrict__ Wq, const float* __restrict__ bq,
    const float* __restrict__ Wk, const float* __restrict__ bk,
    const float* __restrict__ Wv, const float* __restrict__ bv)
{
    __shared__ float As[16][64];   // As[k][m]
    __shared__ float Bs[16][64];   // Bs[k][n]

    const float* W;
    const float* b;
    if (blockIdx.z == 0)      { W = Wq; b = bq; }
    else if (blockIdx.z == 1) { W = Wk; b = bk; }
    else                      { W = Wv; b = bv; }

    const int m0 = blockIdx.x * 64;
    const int n0 = blockIdx.y * 64;
    const int tid = threadIdx.x;
    const int tx = tid & 15, ty = tid >> 4;

    float acc[4][4] = {};

    for (int k0 = 0; k0 < CH; k0 += 16) {
        {
            int k = tid & 15, mb = tid >> 4;
#pragma unroll
            for (int s = 0; s < 4; s++) {
                int m = mb + 16 * s;
                As[k][m] = X[(m0 + m) * CH + k0 + k];
            }
        }
        {
            int n = tid & 63, kb = tid >> 6;
#pragma unroll
            for (int s = 0; s < 4; s++) {
                int k = kb + 4 * s;
                Bs[k][n] = W[(k0 + k) * CH + n0 + n];
            }
        }
        __syncthreads();
#pragma unroll
        for (int k = 0; k < 16; k++) {
            float4 a4 = *(const float4*)&As[k][ty * 4];
            float4 b4 = *(const float4*)&Bs[k][tx * 4];
            float av[4] = {a4.x, a4.y, a4.z, a4.w};
            float bw[4] = {b4.x, b4.y, b4.z, b4.w};
#pragma unroll
            for (int i = 0; i < 4; i++)
#pragma unroll
                for (int j = 0; j < 4; j++)
                    acc[i][j] += av[i] * bw[j];
        }
        __syncthreads();
    }

    float* hiP = (blockIdx.z == 0) ? g_Qhi : g_Khi;
    float* loP = (blockIdx.z == 0) ? g_Qlo : g_Klo;

#pragma unroll
    for (int i = 0; i < 4; i++) {
        int m = m0 + ty * 4 + i;
#pragma unroll
        for (int j = 0; j < 4; j++) {
            int n = n0 + tx * 4 + j;
            float v = acc[i][j] + b[n];
            if (blockIdx.z == 2) {
                g_V[m * CH + n] = v;
            } else {
                float hi = to_tf32(v);
                float lo = to_tf32(v - hi);
                int h = n & 7, dd = n >> 3;
                size_t po = ((size_t)h * NN + m) * DD + dd;
                hiP[po] = hi;
                loP[po] = lo;
            }
        }
    }
}

// ---------------------------------------------------------------------------
// Kernel 2: batched per-head score GEMM, tf32x3: S_h = Q_h @ K_h^T.
// grid = (NN/64 j-tiles, NN/64 i-tiles, NH), 128 threads = 4 warps (2m x 2n),
// warp tile 32x32 (2 x m16, 4 x n8), K = 32 in one shot.
// ---------------------------------------------------------------------------
__global__ __launch_bounds__(128) void score_gemm()
{
    __shared__ float Ah[64][36], Al[64][36];   // Q tile  [i][dd], pad 36
    __shared__ float Bh[64][36], Bl[64][36];   // K tile  [j][dd]

    const int h = blockIdx.z;
    const int i0 = blockIdx.y * 64;
    const int j0 = blockIdx.x * 64;
    const int tid = threadIdx.x;

    const float* qh = &g_Qhi[(size_t)h * NN * DD];
    const float* ql = &g_Qlo[(size_t)h * NN * DD];
    const float* kh = &g_Khi[(size_t)h * NN * DD];
    const float* kl = &g_Klo[(size_t)h * NN * DD];

    // cooperative tile load: 64 rows x 32 floats = 512 float4 per array
    for (int idx = tid; idx < 512; idx += 128) {
        int r = idx >> 3, c4 = (idx & 7) * 4;
        *(float4*)&Ah[r][c4] = *(const float4*)&qh[(i0 + r) * DD + c4];
        *(float4*)&Al[r][c4] = *(const float4*)&ql[(i0 + r) * DD + c4];
        *(float4*)&Bh[r][c4] = *(const float4*)&kh[(j0 + r) * DD + c4];
        *(float4*)&Bl[r][c4] = *(const float4*)&kl[(j0 + r) * DD + c4];
    }
    __syncthreads();

    const int warp = tid >> 5;
    const int lane = tid & 31;
    const int gid = lane >> 2;      // 0..7
    const int tig = lane & 3;       // 0..3
    const int wm = (warp >> 1) * 32;
    const int wn = (warp & 1) * 32;

    float c[2][4][4];
#pragma unroll
    for (int mt = 0; mt < 2; mt++)
#pragma unroll
        for (int nt = 0; nt < 4; nt++)
#pragma unroll
            for (int p = 0; p < 4; p++) c[mt][nt][p] = 0.f;

#pragma unroll
    for (int ks = 0; ks < 4; ks++) {
        const int kb = ks * 8;
        u32 ah[2][4], al[2][4];
#pragma unroll
        for (int mt = 0; mt < 2; mt++) {
            int r0 = wm + mt * 16 + gid;
            ah[mt][0] = __float_as_uint(Ah[r0][kb + tig]);
            ah[mt][1] = __float_as_uint(Ah[r0 + 8][kb + tig]);
            ah[mt][2] = __float_as_uint(Ah[r0][kb + tig + 4]);
            ah[mt][3] = __float_as_uint(Ah[r0 + 8][kb + tig + 4]);
            al[mt][0] = __float_as_uint(Al[r0][kb + tig]);
            al[mt][1] = __float_as_uint(Al[r0 + 8][kb + tig]);
            al[mt][2] = __float_as_uint(Al[r0][kb + tig + 4]);
            al[mt][3] = __float_as_uint(Al[r0 + 8][kb + tig + 4]);
        }
#pragma unroll
        for (int nt = 0; nt < 4; nt++) {
            int jr = wn + nt * 8 + gid;
            u32 bh[2], bl[2];
            bh[0] = __float_as_uint(Bh[jr][kb + tig]);
            bh[1] = __float_as_uint(Bh[jr][kb + tig + 4]);
            bl[0] = __float_as_uint(Bl[jr][kb + tig]);
            bl[1] = __float_as_uint(Bl[jr][kb + tig + 4]);
#pragma unroll
            for (int mt = 0; mt < 2; mt++) {
                mma_tf32(c[mt][nt], ah[mt], bh);   // hi*hi
                mma_tf32(c[mt][nt], ah[mt], bl);   // hi*lo
                mma_tf32(c[mt][nt], al[mt], bh);   // lo*hi
            }
        }
    }

    // epilogue: S[h][i][j]
    float* Sp = &g_S[(size_t)h * NN * NN];
#pragma unroll
    for (int mt = 0; mt < 2; mt++) {
        int i = i0 + wm + mt * 16 + gid;
#pragma unroll
        for (int nt = 0; nt < 4; nt++) {
            int j = j0 + wn + nt * 8 + 2 * tig;
            size_t b0 = (size_t)i * NN + j;
            *(float2*)&Sp[b0] = make_float2(c[mt][nt][0], c[mt][nt][1]);
            *(float2*)&Sp[b0 + (size_t)8 * NN] = make_float2(c[mt][nt][2], c[mt][nt][3]);
        }
    }
}

// ---------------------------------------------------------------------------
// Kernel 3: softmax over heads + attn write + SIMT AV accumulation.
// grid = (128 i-strips, NSPLIT), 256 threads (16x16), occ 2.
// ---------------------------------------------------------------------------
__global__ __launch_bounds__(256, 2) void softmax_av_kernel(
    const float* __restrict__ rel, float* __restrict__ attn_g)
{
    __shared__ float Vs[JC * QROW];

    const int tid = threadIdx.x;
    const int tx = tid & 15, ty = tid >> 4;
    const int ibase = blockIdx.x * 32;
    const int split = blockIdx.y;

    const int NCH = NN / JC;
    const int cs = (split * NCH) / NSPLIT;
    const int ce = ((split + 1) * NCH) / NSPLIT;

    float ao[2][DD];
#pragma unroll
    for (int ii = 0; ii < 2; ii++)
#pragma unroll
        for (int d = 0; d < DD; d++) ao[ii][d] = 0.f;

    const float* v0p = &Vs[tx * QROW];
    const float* v1p = &Vs[(tx + 16) * QROW];

    for (int jc = cs; jc < ce; jc++) {
        const int jbase = jc * JC;
        __syncthreads();
        for (int idx = tid; idx < JC * 64; idx += 256) {
            int r = idx >> 6, c4 = idx & 63;
            *(float4*)&Vs[r * QROW + c4 * 4] =
                *(const float4*)&g_V[(jbase + r) * CH + c4 * 4];
        }
        __syncthreads();

        // ---- load S (8 planes) + rel, softmax over heads, write attn ----
        u64 acc[2][2][4];
#pragma unroll
        for (int ii = 0; ii < 2; ii++) {
            const int ig = ibase + ty * 2 + ii;
#pragma unroll
            for (int jj = 0; jj < 2; jj++) {
                const int jg = jbase + tx + jj * 16;
                const size_t so = (size_t)ig * NN + jg;
                float s[8];
#pragma unroll
                for (int h = 0; h < 8; h++)
                    s[h] = g_S[(size_t)h * NN * NN + so];
                const size_t rb = so * NH;
                float4 r0 = *(const float4*)&rel[rb];
                float4 r1 = *(const float4*)&rel[rb + 4];
                s[0] += r0.x; s[1] += r0.y; s[2] += r0.z; s[3] += r0.w;
                s[4] += r1.x; s[5] += r1.y; s[6] += r1.z; s[7] += r1.w;
                float m = s[0];
#pragma unroll
                for (int h = 1; h < 8; h++) m = fmaxf(m, s[h]);
                float sum = 0.f;
#pragma unroll
                for (int h = 0; h < 8; h++) { s[h] = __expf(s[h] - m); sum += s[h]; }
                const float inv = 1.f / sum;
#pragma unroll
                for (int h = 0; h < 8; h++) s[h] *= inv;
                *(float4*)&attn_g[rb]     = make_float4(s[0], s[1], s[2], s[3]);
                *(float4*)&attn_g[rb + 4] = make_float4(s[4], s[5], s[6], s[7]);
#pragma unroll
                for (int p = 0; p < 4; p++)
                    acc[ii][jj][p] = fpack(s[2 * p], s[2 * p + 1]);
            }
        }

        // ---- AV: ao[ii][dd] += sum_h attn * V[j, dd*8+h] (f32x2 packed) ----
#pragma unroll
        for (int jj = 0; jj < 2; jj++) {
            const float* vp = (jj == 0) ? v0p : v1p;
#pragma unroll 4
            for (int dd = 0; dd < DD; dd++) {
                u64 v2[4];
                ulonglong2 t0 = *(const ulonglong2*)(vp + dd * 8);
                ulonglong2 t1 = *(const ulonglong2*)(vp + dd * 8 + 4);
                v2[0] = t0.x; v2[1] = t0.y; v2[2] = t1.x; v2[3] = t1.y;
                u64 s0 = fmul2(acc[0][jj][0], v2[0]);
                s0 = ffma2(acc[0][jj][1], v2[1], s0);
                s0 = ffma2(acc[0][jj][2], v2[2], s0);
                s0 = ffma2(acc[0][jj][3], v2[3], s0);
                u64 s1 = fmul2(acc[1][jj][0], v2[0]);
                s1 = ffma2(acc[1][jj][1], v2[1], s1);
                s1 = ffma2(acc[1][jj][2], v2[2], s1);
                s1 = ffma2(acc[1][jj][3], v2[3], s1);
                ao[0][dd] += f2lo(s0) + f2hi(s0);
                ao[1][dd] += f2lo(s1) + f2hi(s1);
            }
        }
    }

    // ---- reduce ao across the 16 tx lanes ----
#pragma unroll
    for (int ii = 0; ii < 2; ii++)
#pragma unroll
        for (int dd = 0; dd < DD; dd++) {
            float v = ao[ii][dd];
            v += __shfl_xor_sync(0xffffffffu, v, 1);
            v += __shfl_xor_sync(0xffffffffu, v, 2);
            v += __shfl_xor_sync(0xffffffffu, v, 4);
            v += __shfl_xor_sync(0xffffffffu, v, 8);
            ao[ii][dd] = v;
        }
    if (tx == 0) {
        float* aop = g_AOp[split];
#pragma unroll
        for (int ii = 0; ii < 2; ii++) {
            const int ig = ibase + ty * 2 + ii;
#pragma unroll
            for (int d4 = 0; d4 < DD; d4 += 4)
                *(float4*)&aop[ig * DD + d4] =
                    make_float4(ao[ii][d4], ao[ii][d4 + 1],
                                ao[ii][d4 + 2], ao[ii][d4 + 3]);
        }
    }
}

// ---------------------------------------------------------------------------
// Kernel 4: sum split partials, then out = relu(ao @ W1 + b1) @ W2 + b2.
// ---------------------------------------------------------------------------
__global__ __launch_bounds__(256) void mlp_kernel(
    const float* __restrict__ W1, const float* __restrict__ b1,
    const float* __restrict__ W2, const float* __restrict__ b2,
    float* __restrict__ out)
{
    __shared__ float aos[16][DD];
    __shared__ float hs[16][CH];

    const int tid = threadIdx.x;
    const int r0 = blockIdx.x * 16;

    for (int idx = tid; idx < 16 * DD; idx += 256) {
        const int off = (r0 + idx / DD) * DD + (idx % DD);
        float a = 0.f;
#pragma unroll
        for (int s = 0; s < NSPLIT; s++) a += g_AOp[s][off];
        aos[idx / DD][idx % DD] = a;
    }
    __syncthreads();

    const int c = tid;
    float w[DD];
#pragma unroll
    for (int k = 0; k < DD; k++) w[k] = W1[k * CH + c];
    const float bb1 = b1[c];
#pragma unroll 4
    for (int r = 0; r < 16; r++) {
        float a = bb1;
#pragma unroll
        for (int k = 0; k < DD; k++) a += aos[r][k] * w[k];
        hs[r][c] = fmaxf(a, 0.f);
    }
    __syncthreads();

    float acc2[16];
    const float bb2 = b2[c];
#pragma unroll
    for (int r = 0; r < 16; r++) acc2[r] = bb2;
#pragma unroll 4
    for (int k = 0; k < CH; k++) {
        const float wv = W2[k * CH + c];
#pragma unroll
        for (int r = 0; r < 16; r++) acc2[r] += hs[r][k] * wv;
    }
#pragma unroll
    for (int r = 0; r < 16; r++) out[(r0 + r) * CH + c] = acc2[r];
}

// ---------------------------------------------------------------------------
extern "C" void kernel_launch(void* const* d_in, const int* in_sizes, int n_in,
                              void* d_out, int out_size)
{
    const float* X   = (const float*)d_in[0];
    const float* rel = (const float*)d_in[1];
    // d_in[2] = num_nodes (unused; N fixed at 4096)
    const float* Wq = (const float*)d_in[3];
    const float* bq = (const float*)d_in[4];
    const float* Wk = (const float*)d_in[5];
    const float* bk = (const float*)d_in[6];
    const float* Wv = (const float*)d_in[7];
    const float* bv = (const float*)d_in[8];
    const float* W1 = (const float*)d_in[9];
    const float* b1 = (const float*)d_in[10];
    const float* W2 = (const float*)d_in[11];
    const float* b2 = (const float*)d_in[12];

    float* out    = (float*)d_out;           // [4096, 256]
    float* attn_g = out + (size_t)NN * CH;   // [4096, 4096, 8]

    qkv_kernel<<<dim3(64, 4, 3), 256>>>(X, Wq, bq, Wk, bk, Wv, bv);
    score_gemm<<<dim3(NN / 64, NN / 64, NH), 128>>>();
    softmax_av_kernel<<<dim3(NN / 32, NSPLIT), 256>>>(rel, attn_g);
    mlp_kernel<<<NN / 16, 256>>>(W1, b1, W2, b2, out);
}